// round 7
// baseline (speedup 1.0000x reference)
#include <cuda_runtime.h>
#include <math.h>

#define NB 16
#define NC 256
#define HW_ 4096

typedef unsigned long long u64;

// Scratch (device globals; no allocation in kernel_launch)
__device__ float g_t[NB*NC*HW_];       // ctx channels of conv1x1 output
__device__ float g_gp[2][NB*4*HW_];    // gate channel partials (2-way c-split)
__device__ float g_gates[NB*4*HW_];    // combined gates
__device__ float g_ctxall[NB*NC*HW_];  // final ctx_all
__device__ float g_kp[4][NB*HW_];      // key logit partials (4-way c-split)
__device__ float g_k[NB*HW_];          // softmax result
__device__ float g_qk[NB*NC];
__device__ float g_v[NB*NC];           // broadcast add vector

__device__ __forceinline__ float gelu_f(float v) {
    return 0.5f * v * (1.0f + erff(v * 0.70710678118654752f));
}

__device__ __forceinline__ void ffma2(u64 &d, u64 a, u64 b) {
    asm("fma.rn.f32x2 %0, %1, %2, %3;" : "=l"(d) : "l"(a), "l"(b), "l"(d));
}
__device__ __forceinline__ void unpack2(float &lo, float &hi, u64 d) {
    asm("mov.b64 {%0, %1}, %2;" : "=f"(lo), "=f"(hi) : "l"(d));
}

// ---------------------------------------------------------------------------
// Kernel 1: conv1x1 main GEMM, f32x2 FMAs with DUPLICATED-broadcast A smem:
// each w value stored twice so the packed broadcast operand is a single
// 64-bit LDS — no pack MOVs in the inner loop (R5 lesson).
// Per batch: T(256,4096) = W(256,256) * X(256,4096)
// Tile 64(M=o) x 128(N=pixels), 128 threads, 8x8 microtile, BK=16.
// ---------------------------------------------------------------------------
__global__ __launch_bounds__(128) void gemm1_kernel(const float* __restrict__ x,
                                                    const float* __restrict__ w,
                                                    const float* __restrict__ bias) {
    __shared__ __align__(16) float Ad[16][128];   // duplicated: [kk][2*mm(+1)]
    __shared__ __align__(16) float Bs[16][128];
    const int b = blockIdx.z;
    const int oBase = blockIdx.y * 64;
    const int nBase = blockIdx.x * 128;
    const float* xb = x + (size_t)b * NC * HW_;
    const int tid = threadIdx.x;
    const int tm = tid >> 4, tn = tid & 15;

    u64 acc2[8][4];
#pragma unroll
    for (int i = 0; i < 8; i++)
#pragma unroll
        for (int j = 0; j < 4; j++) acc2[i][j] = 0ull;

    for (int c0 = 0; c0 < NC; c0 += 16) {
#pragma unroll
        for (int r = 0; r < 8; r++) {
            int i = tid + r * 128;           // 0..1023
            int mm = i >> 4, kk = i & 15;
            float v = w[(oBase + mm) * NC + c0 + kk];
            Ad[kk][2 * mm] = v;
            Ad[kk][2 * mm + 1] = v;
        }
#pragma unroll
        for (int kk = 0; kk < 16; kk++)
            Bs[kk][tid] = xb[(size_t)(c0 + kk) * HW_ + nBase + tid];
        __syncthreads();

#pragma unroll
        for (int kk = 0; kk < 16; kk++) {
            ulonglong2 aq0 = *(const ulonglong2*)&Ad[kk][tm * 16];
            ulonglong2 aq1 = *(const ulonglong2*)&Ad[kk][tm * 16 + 4];
            ulonglong2 aq2 = *(const ulonglong2*)&Ad[kk][tm * 16 + 8];
            ulonglong2 aq3 = *(const ulonglong2*)&Ad[kk][tm * 16 + 12];
            u64 a2[8] = {aq0.x, aq0.y, aq1.x, aq1.y, aq2.x, aq2.y, aq3.x, aq3.y};
            ulonglong2 bq0 = *(const ulonglong2*)&Bs[kk][tn * 8];
            ulonglong2 bq1 = *(const ulonglong2*)&Bs[kk][tn * 8 + 4];
            u64 bv[4] = {bq0.x, bq0.y, bq1.x, bq1.y};
#pragma unroll
            for (int i = 0; i < 8; i++)
#pragma unroll
                for (int j = 0; j < 4; j++)
                    ffma2(acc2[i][j], a2[i], bv[j]);
        }
        __syncthreads();
    }

#pragma unroll
    for (int i = 0; i < 8; i++) {
        int o = oBase + tm * 8 + i;
        float bvv = bias[o];
        float* dst = g_t + ((size_t)b * NC + o) * HW_ + nBase + tn * 8;
        float l0, h0, l1, h1, l2, h2, l3, h3;
        unpack2(l0, h0, acc2[i][0]); unpack2(l1, h1, acc2[i][1]);
        unpack2(l2, h2, acc2[i][2]); unpack2(l3, h3, acc2[i][3]);
        float4 v0 = make_float4(l0 + bvv, h0 + bvv, l1 + bvv, h1 + bvv);
        float4 v1 = make_float4(l2 + bvv, h2 + bvv, l3 + bvv, h3 + bvv);
        *(float4*)dst = v0;
        *(float4*)(dst + 4) = v1;
    }
}

// ---------------------------------------------------------------------------
// Kernel 2: gate channels (o = 256..259). 2-way channel split for occupancy.
// ---------------------------------------------------------------------------
__global__ __launch_bounds__(256) void gates_kernel(const float* __restrict__ x,
                                                    const float* __restrict__ w,
                                                    const float* __restrict__ bias) {
    __shared__ float wg[4 * 128];
    const int tid = threadIdx.x;
    const int b = blockIdx.y;
    const int part = blockIdx.z;
    const int n = blockIdx.x * 256 + tid;
    if (tid < 128) {
#pragma unroll
        for (int r = 0; r < 4; r++) wg[r * 128 + tid] = w[(NC + r) * NC + part * 128 + tid];
    }
    __syncthreads();

    const float* xb = x + ((size_t)b * NC + part * 128) * HW_ + n;
    float a0 = 0.f, a1 = 0.f, a2 = 0.f, a3 = 0.f;
    if (part == 0) { a0 = bias[256]; a1 = bias[257]; a2 = bias[258]; a3 = bias[259]; }
#pragma unroll 4
    for (int cc = 0; cc < 128; cc++) {
        float xv = xb[(size_t)cc * HW_];
        a0 = fmaf(wg[cc], xv, a0);
        a1 = fmaf(wg[128 + cc], xv, a1);
        a2 = fmaf(wg[256 + cc], xv, a2);
        a3 = fmaf(wg[384 + cc], xv, a3);
    }
    float* gd = g_gp[part] + (size_t)b * 4 * HW_ + n;
    gd[0] = a0; gd[HW_] = a1; gd[2 * HW_] = a2; gd[3 * HW_] = a3;
}

// ---------------------------------------------------------------------------
// Kernel 2b: combine gate partials (tiny; 2 MB total).
// ---------------------------------------------------------------------------
__global__ __launch_bounds__(256) void gatecomb_kernel() {
    const int i = blockIdx.x * 256 + threadIdx.x;  // float4 index, 65536 total
    float4 a = ((const float4*)g_gp[0])[i];
    float4 c = ((const float4*)g_gp[1])[i];
    a.x += c.x; a.y += c.y; a.z += c.z; a.w += c.w;
    ((float4*)g_gates)[i] = a;
}

// ---------------------------------------------------------------------------
// Kernel 3: fused depthwise chain — measured-best geometry (R4): 256 threads,
// 16 rows/thread, scalar FMA, column-register reuse. One block per (b,c).
// ---------------------------------------------------------------------------
#define PW 70  // 64 + 2*3 halo

template<int K>
__device__ __forceinline__ void conv_stage(const float* __restrict__ buf,
                                           const float* __restrict__ filt,
                                           int x0, int y0, float s[16]) {
    constexpr int YE = 16 + K - 1;
#pragma unroll
    for (int i = 0; i < 16; i++) s[i] = 0.f;
#pragma unroll
    for (int dx = 0; dx < K; dx++) {
        float col[YE];
#pragma unroll
        for (int i = 0; i < YE; i++) col[i] = buf[(y0 + i) * PW + x0 + dx];
#pragma unroll
        for (int dy = 0; dy < K; dy++) {
            const float f = filt[dy * K + dx];
#pragma unroll
            for (int i = 0; i < 16; i++) s[i] = fmaf(f, col[i + dy], s[i]);
        }
    }
}

__global__ __launch_bounds__(256) void dwchain_kernel(const float* __restrict__ fw3,
                                                      const float* __restrict__ fw5,
                                                      const float* __restrict__ fw7) {
    __shared__ float buf0[PW * PW];
    __shared__ float buf1[PW * PW];
    __shared__ float filt[49];
    __shared__ float red[256];
    const int bc = blockIdx.x;              // = b*256 + c
    const int b = bc >> 8, c = bc & 255;
    const int tid = threadIdx.x;
    const int x = tid & 63, yg = tid >> 6;  // thread owns column x, rows yg*16..+15

    for (int i = tid; i < PW * PW; i += 256) { buf0[i] = 0.f; buf1[i] = 0.f; }
    if (tid < 9) filt[tid] = fw3[c * 9 + tid];
    __syncthreads();

    const float* src = g_t + (size_t)bc * HW_;
#pragma unroll
    for (int i = 0; i < 16; i++) {
        int y = yg * 16 + i;
        buf0[(y + 3) * PW + x + 3] = src[y * 64 + x];
    }
    __syncthreads();

    const float* gts = g_gates + (size_t)b * 4 * HW_;
    float acc[16];
#pragma unroll
    for (int i = 0; i < 16; i++) acc[i] = 0.f;
    float s[16];

    // --- stage 1: 3x3, buf0 -> buf1 ---
    conv_stage<3>(buf0, filt, x + 2, yg * 16 + 2, s);
#pragma unroll
    for (int i = 0; i < 16; i++) {
        int y = yg * 16 + i;
        int p = y * 64 + x;
        float g = gelu_f(s[i]);
        buf1[(y + 3) * PW + x + 3] = g;
        acc[i] = fmaf(g, gts[p], acc[i]);
    }
    __syncthreads();
    if (tid < 25) filt[tid] = fw5[c * 25 + tid];
    __syncthreads();

    // --- stage 2: 5x5, buf1 -> buf0 ---
    conv_stage<5>(buf1, filt, x + 1, yg * 16 + 1, s);
#pragma unroll
    for (int i = 0; i < 16; i++) {
        int y = yg * 16 + i;
        int p = y * 64 + x;
        float g = gelu_f(s[i]);
        buf0[(y + 3) * PW + x + 3] = g;
        acc[i] = fmaf(g, gts[HW_ + p], acc[i]);
    }
    __syncthreads();
    if (tid < 49) filt[tid] = fw7[c * 49 + tid];
    __syncthreads();

    // --- stage 3: 7x7, buf0 -> registers only, plus plane sum for global ctx ---
    conv_stage<7>(buf0, filt, x, yg * 16, s);
    float sum7 = 0.f;
#pragma unroll
    for (int i = 0; i < 16; i++) {
        int y = yg * 16 + i;
        int p = y * 64 + x;
        float g = gelu_f(s[i]);
        acc[i] = fmaf(g, gts[2 * HW_ + p], acc[i]);
        sum7 += g;
    }
    red[tid] = sum7;
    __syncthreads();
    for (int st = 128; st > 0; st >>= 1) {
        if (tid < st) red[tid] += red[tid + st];
        __syncthreads();
    }
    float mean = red[0] * (1.0f / 4096.0f);

    float* dst = g_ctxall + (size_t)bc * HW_;
#pragma unroll
    for (int i = 0; i < 16; i++) {
        int y = yg * 16 + i;
        int p = y * 64 + x;
        dst[p] = fmaf(mean, gts[3 * HW_ + p], acc[i]);
    }
}

// ---------------------------------------------------------------------------
// Kernel 4: key logit partials. 4-way channel split, bias dropped (cancels
// exactly under softmax max-subtraction).
// ---------------------------------------------------------------------------
__global__ __launch_bounds__(256) void key_kernel(const float* __restrict__ key_w) {
    __shared__ float kw[64];
    const int tid = threadIdx.x;
    const int b = blockIdx.y;
    const int part = blockIdx.z;
    const int n = blockIdx.x * 256 + tid;
    if (tid < 64) kw[tid] = key_w[part * 64 + tid];
    __syncthreads();
    const float* ca = g_ctxall + ((size_t)b * NC + part * 64) * HW_ + n;
    float a0 = 0.f, a1 = 0.f;
#pragma unroll 4
    for (int cc = 0; cc < 64; cc += 2) {
        a0 = fmaf(kw[cc], ca[(size_t)cc * HW_], a0);
        a1 = fmaf(kw[cc + 1], ca[(size_t)(cc + 1) * HW_], a1);
    }
    g_kp[part][b * HW_ + n] = a0 + a1;
}

// ---------------------------------------------------------------------------
// Kernel 5: sum partials + softmax over 4096 per batch.
// ---------------------------------------------------------------------------
__global__ __launch_bounds__(1024) void softmax_kernel() {
    __shared__ float red[1024];
    const int b = blockIdx.x, tid = threadIdx.x;
    float v[4];
    float mx = -1e30f;
#pragma unroll
    for (int i = 0; i < 4; i++) {
        int n = b * HW_ + tid + i * 1024;
        v[i] = g_kp[0][n] + g_kp[1][n] + g_kp[2][n] + g_kp[3][n];
        mx = fmaxf(mx, v[i]);
    }
    red[tid] = mx;
    __syncthreads();
    for (int st = 512; st > 0; st >>= 1) {
        if (tid < st) red[tid] = fmaxf(red[tid], red[tid + st]);
        __syncthreads();
    }
    mx = red[0];
    __syncthreads();
    float s = 0.f;
#pragma unroll
    for (int i = 0; i < 4; i++) { v[i] = expf(v[i] - mx); s += v[i]; }
    red[tid] = s;
    __syncthreads();
    for (int st = 512; st > 0; st >>= 1) {
        if (tid < st) red[tid] += red[tid + st];
        __syncthreads();
    }
    float inv = 1.0f / red[0];
#pragma unroll
    for (int i = 0; i < 4; i++) g_k[b * HW_ + tid + i * 1024] = v[i] * inv;
}

// ---------------------------------------------------------------------------
// Kernel 6: qk[b,c] = sum_n ctx_all[b,c,n] * k[b,n]  (one block per (b,c))
// ---------------------------------------------------------------------------
__global__ __launch_bounds__(256) void qk_kernel() {
    __shared__ float red[256];
    const int bc = blockIdx.x;
    const int b = bc >> 8;
    const float4* ca = (const float4*)(g_ctxall + (size_t)bc * HW_);
    const float4* kk = (const float4*)(g_k + b * HW_);
    float s = 0.f;
    for (int i = threadIdx.x; i < 1024; i += 256) {
        float4 a = ca[i], kv = kk[i];
        s += a.x * kv.x + a.y * kv.y + a.z * kv.z + a.w * kv.w;
    }
    red[threadIdx.x] = s;
    __syncthreads();
    for (int st = 128; st > 0; st >>= 1) {
        if (threadIdx.x < st) red[threadIdx.x] += red[threadIdx.x + st];
        __syncthreads();
    }
    if (threadIdx.x == 0) g_qk[bc] = red[0];
}

// ---------------------------------------------------------------------------
// Kernel 7: per-batch tiny MLP: v1 (16) -> layernorm -> relu -> v2 (256)
// ---------------------------------------------------------------------------
__global__ __launch_bounds__(256) void mlp_kernel(const float* __restrict__ v1_w,
                                                  const float* __restrict__ v1_b,
                                                  const float* __restrict__ ln_w,
                                                  const float* __restrict__ ln_b,
                                                  const float* __restrict__ v2_w,
                                                  const float* __restrict__ v2_b) {
    __shared__ float qk[256];
    __shared__ float vv[16];
    const int b = blockIdx.x, tid = threadIdx.x;
    qk[tid] = g_qk[b * 256 + tid];
    __syncthreads();
    if (tid < 16) {
        float s = v1_b[tid];
        for (int cc = 0; cc < 256; cc++) s = fmaf(v1_w[tid * 256 + cc], qk[cc], s);
        vv[tid] = s;
    }
    __syncthreads();
    if (tid == 0) {
        float m = 0.f;
        for (int o = 0; o < 16; o++) m += vv[o];
        m *= (1.f / 16.f);
        float var = 0.f;
        for (int o = 0; o < 16; o++) { float d = vv[o] - m; var += d * d; }
        var *= (1.f / 16.f);
        float inv = rsqrtf(var + 1e-5f);
        for (int o = 0; o < 16; o++) {
            float t = (vv[o] - m) * inv * ln_w[o] + ln_b[o];
            vv[o] = fmaxf(t, 0.f);
        }
    }
    __syncthreads();
    float s = v2_b[tid];
#pragma unroll
    for (int o = 0; o < 16; o++) s = fmaf(v2_w[tid * 16 + o], vv[o], s);
    g_v[b * 256 + tid] = s;
}

// ---------------------------------------------------------------------------
// Kernel 8: out = ctx_all + v (broadcast over pixels), vectorized float4.
// ---------------------------------------------------------------------------
__global__ __launch_bounds__(256) void final_kernel(float* __restrict__ out) {
    const int idx = blockIdx.x * 256 + threadIdx.x;  // float4 index
    float4 v = ((const float4*)g_ctxall)[idx];
    float add = g_v[idx >> 10];  // 1024 float4 per (b,c) plane
    v.x += add; v.y += add; v.z += add; v.w += add;
    ((float4*)out)[idx] = v;
}

// ---------------------------------------------------------------------------
extern "C" void kernel_launch(void* const* d_in, const int* in_sizes, int n_in,
                              void* d_out, int out_size) {
    const float* x      = (const float*)d_in[0];
    const float* conv_w = (const float*)d_in[1];
    const float* conv_b = (const float*)d_in[2];
    const float* fw3    = (const float*)d_in[3];
    const float* fw5    = (const float*)d_in[4];
    const float* fw7    = (const float*)d_in[5];
    const float* key_w  = (const float*)d_in[6];
    const float* v1_w   = (const float*)d_in[8];
    const float* v1_b   = (const float*)d_in[9];
    const float* ln_w   = (const float*)d_in[10];
    const float* ln_b   = (const float*)d_in[11];
    const float* v2_w   = (const float*)d_in[12];
    const float* v2_b   = (const float*)d_in[13];
    float* out = (float*)d_out;

    gemm1_kernel<<<dim3(32, 4, 16), 128>>>(x, conv_w, conv_b);
    gates_kernel<<<dim3(16, 16, 2), 256>>>(x, conv_w, conv_b);
    gatecomb_kernel<<<256, 256>>>();
    dwchain_kernel<<<4096, 256>>>(fw3, fw5, fw7);
    key_kernel<<<dim3(16, 16, 4), 256>>>(key_w);
    softmax_kernel<<<16, 1024>>>();
    qk_kernel<<<4096, 256>>>();
    mlp_kernel<<<16, 256>>>(v1_w, v1_b, ln_w, ln_b, v2_w, v2_b);
    final_kernel<<<16384, 256>>>(out);
}

// round 8
// speedup vs baseline: 1.8761x; 1.8761x over previous
#include <cuda_runtime.h>
#include <math.h>

#define NB 16
#define NC 256
#define HW_ 4096

typedef unsigned long long u64;

// Scratch (device globals; no allocation in kernel_launch)
__device__ float g_t[NB*NC*HW_];       // ctx channels of conv1x1 output
__device__ float g_gp[2][NB*4*HW_];    // gate channel partials (2-way c-split)
__device__ float g_gates[NB*4*HW_];    // combined gates
__device__ float g_ctxall[NB*NC*HW_];  // final ctx_all
__device__ float g_kp[4][NB*HW_];      // key logit partials (4-way c-split)
__device__ float g_k[NB*HW_];          // softmax result
__device__ float g_qk[NB*NC];
__device__ float g_v[NB*NC];           // broadcast add vector

__device__ __forceinline__ float gelu_f(float v) {
    return 0.5f * v * (1.0f + erff(v * 0.70710678118654752f));
}

__device__ __forceinline__ u64 pack2(float lo, float hi) {
    u64 d; asm("mov.b64 %0, {%1, %2};" : "=l"(d) : "f"(lo), "f"(hi)); return d;
}
__device__ __forceinline__ void ffma2(u64 &d, u64 a, u64 b) {
    asm("fma.rn.f32x2 %0, %1, %2, %3;" : "=l"(d) : "l"(a), "l"(b), "l"(d));
}
__device__ __forceinline__ void unpack2(float &lo, float &hi, u64 d) {
    asm("mov.b64 {%0, %1}, %2;" : "=f"(lo), "=f"(hi) : "l"(d));
}

// ---------------------------------------------------------------------------
// Kernel 1: conv1x1 main GEMM — R4-measured-good version: packed f32x2 FMAs,
// scalar-LDS A broadcast + pack2 (NOT duplicated smem — R7 showed that
// bank-conflicts), single-buffered smem.
// Per batch: T(256,4096) = W(256,256) * X(256,4096)
// Tile 64(M=o) x 128(N=pixels), 128 threads, 8x8 microtile, BK=16.
// ---------------------------------------------------------------------------
__global__ __launch_bounds__(128) void gemm1_kernel(const float* __restrict__ x,
                                                    const float* __restrict__ w,
                                                    const float* __restrict__ bias) {
    __shared__ __align__(16) float As[16][64];
    __shared__ __align__(16) float Bs[16][128];
    const int b = blockIdx.z;
    const int oBase = blockIdx.y * 64;
    const int nBase = blockIdx.x * 128;
    const float* xb = x + (size_t)b * NC * HW_;
    const int tid = threadIdx.x;
    const int tm = tid >> 4, tn = tid & 15;

    u64 acc2[8][4];
#pragma unroll
    for (int i = 0; i < 8; i++)
#pragma unroll
        for (int j = 0; j < 4; j++) acc2[i][j] = 0ull;

    for (int c0 = 0; c0 < NC; c0 += 16) {
#pragma unroll
        for (int r = 0; r < 8; r++) {
            int i = tid + r * 128;           // 0..1023
            int mm = i >> 4, kk = i & 15;
            As[kk][mm] = w[(oBase + mm) * NC + c0 + kk];
        }
#pragma unroll
        for (int kk = 0; kk < 16; kk++)
            Bs[kk][tid] = xb[(size_t)(c0 + kk) * HW_ + nBase + tid];
        __syncthreads();

#pragma unroll
        for (int kk = 0; kk < 16; kk++) {
            float4 a0 = *(const float4*)&As[kk][tm * 8];
            float4 a1 = *(const float4*)&As[kk][tm * 8 + 4];
            ulonglong2 bq0 = *(const ulonglong2*)&Bs[kk][tn * 8];
            ulonglong2 bq1 = *(const ulonglong2*)&Bs[kk][tn * 8 + 4];
            u64 bv[4] = {bq0.x, bq0.y, bq1.x, bq1.y};
            u64 a2[8];
            a2[0] = pack2(a0.x, a0.x); a2[1] = pack2(a0.y, a0.y);
            a2[2] = pack2(a0.z, a0.z); a2[3] = pack2(a0.w, a0.w);
            a2[4] = pack2(a1.x, a1.x); a2[5] = pack2(a1.y, a1.y);
            a2[6] = pack2(a1.z, a1.z); a2[7] = pack2(a1.w, a1.w);
#pragma unroll
            for (int i = 0; i < 8; i++)
#pragma unroll
                for (int j = 0; j < 4; j++)
                    ffma2(acc2[i][j], a2[i], bv[j]);
        }
        __syncthreads();
    }

#pragma unroll
    for (int i = 0; i < 8; i++) {
        int o = oBase + tm * 8 + i;
        float bvv = bias[o];
        float* dst = g_t + ((size_t)b * NC + o) * HW_ + nBase + tn * 8;
        float l0, h0, l1, h1, l2, h2, l3, h3;
        unpack2(l0, h0, acc2[i][0]); unpack2(l1, h1, acc2[i][1]);
        unpack2(l2, h2, acc2[i][2]); unpack2(l3, h3, acc2[i][3]);
        float4 v0 = make_float4(l0 + bvv, h0 + bvv, l1 + bvv, h1 + bvv);
        float4 v1 = make_float4(l2 + bvv, h2 + bvv, l3 + bvv, h3 + bvv);
        *(float4*)dst = v0;
        *(float4*)(dst + 4) = v1;
    }
}

// ---------------------------------------------------------------------------
// Kernel 2: gate channels (o = 256..259). 2-way channel split for occupancy.
// ---------------------------------------------------------------------------
__global__ __launch_bounds__(256) void gates_kernel(const float* __restrict__ x,
                                                    const float* __restrict__ w,
                                                    const float* __restrict__ bias) {
    __shared__ float wg[4 * 128];
    const int tid = threadIdx.x;
    const int b = blockIdx.y;
    const int part = blockIdx.z;
    const int n = blockIdx.x * 256 + tid;
    if (tid < 128) {
#pragma unroll
        for (int r = 0; r < 4; r++) wg[r * 128 + tid] = w[(NC + r) * NC + part * 128 + tid];
    }
    __syncthreads();

    const float* xb = x + ((size_t)b * NC + part * 128) * HW_ + n;
    float a0 = 0.f, a1 = 0.f, a2 = 0.f, a3 = 0.f;
    if (part == 0) { a0 = bias[256]; a1 = bias[257]; a2 = bias[258]; a3 = bias[259]; }
#pragma unroll 4
    for (int cc = 0; cc < 128; cc++) {
        float xv = xb[(size_t)cc * HW_];
        a0 = fmaf(wg[cc], xv, a0);
        a1 = fmaf(wg[128 + cc], xv, a1);
        a2 = fmaf(wg[256 + cc], xv, a2);
        a3 = fmaf(wg[384 + cc], xv, a3);
    }
    float* gd = g_gp[part] + (size_t)b * 4 * HW_ + n;
    gd[0] = a0; gd[HW_] = a1; gd[2 * HW_] = a2; gd[3 * HW_] = a3;
}

// ---------------------------------------------------------------------------
// Kernel 2b: combine gate partials (tiny; 2 MB total).
// ---------------------------------------------------------------------------
__global__ __launch_bounds__(256) void gatecomb_kernel() {
    const int i = blockIdx.x * 256 + threadIdx.x;  // float4 index, 65536 total
    float4 a = ((const float4*)g_gp[0])[i];
    float4 c = ((const float4*)g_gp[1])[i];
    a.x += c.x; a.y += c.y; a.z += c.z; a.w += c.w;
    ((float4*)g_gates)[i] = a;
}

// ---------------------------------------------------------------------------
// Kernel 3: fused depthwise chain, scalar FMA + column-register reuse,
// 256 threads x 16 rows, capped at 64 regs (minctasm=4) for occupancy.
// ---------------------------------------------------------------------------
#define PW 70  // 64 + 2*3 halo

template<int K>
__device__ __forceinline__ void conv_stage(const float* __restrict__ buf,
                                           const float* __restrict__ filt,
                                           int x0, int y0, float s[16]) {
    constexpr int YE = 16 + K - 1;
#pragma unroll
    for (int i = 0; i < 16; i++) s[i] = 0.f;
#pragma unroll
    for (int dx = 0; dx < K; dx++) {
        float col[YE];
#pragma unroll
        for (int i = 0; i < YE; i++) col[i] = buf[(y0 + i) * PW + x0 + dx];
#pragma unroll
        for (int dy = 0; dy < K; dy++) {
            const float f = filt[dy * K + dx];
#pragma unroll
            for (int i = 0; i < 16; i++) s[i] = fmaf(f, col[i + dy], s[i]);
        }
    }
}

__global__ __launch_bounds__(256, 4) void dwchain_kernel(const float* __restrict__ fw3,
                                                         const float* __restrict__ fw5,
                                                         const float* __restrict__ fw7) {
    __shared__ float buf0[PW * PW];
    __shared__ float buf1[PW * PW];
    __shared__ float filt[49];
    __shared__ float red[256];
    const int bc = blockIdx.x;              // = b*256 + c
    const int b = bc >> 8, c = bc & 255;
    const int tid = threadIdx.x;
    const int x = tid & 63, yg = tid >> 6;  // thread owns column x, rows yg*16..+15

    for (int i = tid; i < PW * PW; i += 256) { buf0[i] = 0.f; buf1[i] = 0.f; }
    if (tid < 9) filt[tid] = fw3[c * 9 + tid];
    __syncthreads();

    const float* src = g_t + (size_t)bc * HW_;
#pragma unroll
    for (int i = 0; i < 16; i++) {
        int y = yg * 16 + i;
        buf0[(y + 3) * PW + x + 3] = src[y * 64 + x];
    }
    __syncthreads();

    const float* gts = g_gates + (size_t)b * 4 * HW_;
    float acc[16];
#pragma unroll
    for (int i = 0; i < 16; i++) acc[i] = 0.f;
    float s[16];

    // --- stage 1: 3x3, buf0 -> buf1 ---
    conv_stage<3>(buf0, filt, x + 2, yg * 16 + 2, s);
#pragma unroll
    for (int i = 0; i < 16; i++) {
        int y = yg * 16 + i;
        int p = y * 64 + x;
        float g = gelu_f(s[i]);
        buf1[(y + 3) * PW + x + 3] = g;
        acc[i] = fmaf(g, gts[p], acc[i]);
    }
    __syncthreads();
    if (tid < 25) filt[tid] = fw5[c * 25 + tid];
    __syncthreads();

    // --- stage 2: 5x5, buf1 -> buf0 ---
    conv_stage<5>(buf1, filt, x + 1, yg * 16 + 1, s);
#pragma unroll
    for (int i = 0; i < 16; i++) {
        int y = yg * 16 + i;
        int p = y * 64 + x;
        float g = gelu_f(s[i]);
        buf0[(y + 3) * PW + x + 3] = g;
        acc[i] = fmaf(g, gts[HW_ + p], acc[i]);
    }
    __syncthreads();
    if (tid < 49) filt[tid] = fw7[c * 49 + tid];
    __syncthreads();

    // --- stage 3: 7x7, buf0 -> registers only, plus plane sum for global ctx ---
    conv_stage<7>(buf0, filt, x, yg * 16, s);
    float sum7 = 0.f;
#pragma unroll
    for (int i = 0; i < 16; i++) {
        int y = yg * 16 + i;
        int p = y * 64 + x;
        float g = gelu_f(s[i]);
        acc[i] = fmaf(g, gts[2 * HW_ + p], acc[i]);
        sum7 += g;
    }
    red[tid] = sum7;
    __syncthreads();
    for (int st = 128; st > 0; st >>= 1) {
        if (tid < st) red[tid] += red[tid + st];
        __syncthreads();
    }
    float mean = red[0] * (1.0f / 4096.0f);

    float* dst = g_ctxall + (size_t)bc * HW_;
#pragma unroll
    for (int i = 0; i < 16; i++) {
        int y = yg * 16 + i;
        int p = y * 64 + x;
        dst[p] = fmaf(mean, gts[3 * HW_ + p], acc[i]);
    }
}

// ---------------------------------------------------------------------------
// Kernel 4: key logit partials. 4-way channel split, bias dropped (cancels
// exactly under softmax max-subtraction).
// ---------------------------------------------------------------------------
__global__ __launch_bounds__(256) void key_kernel(const float* __restrict__ key_w) {
    __shared__ float kw[64];
    const int tid = threadIdx.x;
    const int b = blockIdx.y;
    const int part = blockIdx.z;
    const int n = blockIdx.x * 256 + tid;
    if (tid < 64) kw[tid] = key_w[part * 64 + tid];
    __syncthreads();
    const float* ca = g_ctxall + ((size_t)b * NC + part * 64) * HW_ + n;
    float a0 = 0.f, a1 = 0.f;
#pragma unroll 4
    for (int cc = 0; cc < 64; cc += 2) {
        a0 = fmaf(kw[cc], ca[(size_t)cc * HW_], a0);
        a1 = fmaf(kw[cc + 1], ca[(size_t)(cc + 1) * HW_], a1);
    }
    g_kp[part][b * HW_ + n] = a0 + a1;
}

// ---------------------------------------------------------------------------
// Kernel 5: sum partials + softmax over 4096 per batch.
// ---------------------------------------------------------------------------
__global__ __launch_bounds__(1024) void softmax_kernel() {
    __shared__ float red[1024];
    const int b = blockIdx.x, tid = threadIdx.x;
    float v[4];
    float mx = -1e30f;
#pragma unroll
    for (int i = 0; i < 4; i++) {
        int n = b * HW_ + tid + i * 1024;
        v[i] = g_kp[0][n] + g_kp[1][n] + g_kp[2][n] + g_kp[3][n];
        mx = fmaxf(mx, v[i]);
    }
    red[tid] = mx;
    __syncthreads();
    for (int st = 512; st > 0; st >>= 1) {
        if (tid < st) red[tid] = fmaxf(red[tid], red[tid + st]);
        __syncthreads();
    }
    mx = red[0];
    __syncthreads();
    float s = 0.f;
#pragma unroll
    for (int i = 0; i < 4; i++) { v[i] = expf(v[i] - mx); s += v[i]; }
    red[tid] = s;
    __syncthreads();
    for (int st = 512; st > 0; st >>= 1) {
        if (tid < st) red[tid] += red[tid + st];
        __syncthreads();
    }
    float inv = 1.0f / red[0];
#pragma unroll
    for (int i = 0; i < 4; i++) g_k[b * HW_ + tid + i * 1024] = v[i] * inv;
}

// ---------------------------------------------------------------------------
// Kernel 6: qk[b,c] = sum_n ctx_all[b,c,n] * k[b,n]  (one block per (b,c))
// ---------------------------------------------------------------------------
__global__ __launch_bounds__(256) void qk_kernel() {
    __shared__ float red[256];
    const int bc = blockIdx.x;
    const int b = bc >> 8;
    const float4* ca = (const float4*)(g_ctxall + (size_t)bc * HW_);
    const float4* kk = (const float4*)(g_k + b * HW_);
    float s = 0.f;
    for (int i = threadIdx.x; i < 1024; i += 256) {
        float4 a = ca[i], kv = kk[i];
        s += a.x * kv.x + a.y * kv.y + a.z * kv.z + a.w * kv.w;
    }
    red[threadIdx.x] = s;
    __syncthreads();
    for (int st = 128; st > 0; st >>= 1) {
        if (threadIdx.x < st) red[threadIdx.x] += red[threadIdx.x + st];
        __syncthreads();
    }
    if (threadIdx.x == 0) g_qk[bc] = red[0];
}

// ---------------------------------------------------------------------------
// Kernel 7: per-batch tiny MLP: v1 (16) -> layernorm -> relu -> v2 (256)
// ---------------------------------------------------------------------------
__global__ __launch_bounds__(256) void mlp_kernel(const float* __restrict__ v1_w,
                                                  const float* __restrict__ v1_b,
                                                  const float* __restrict__ ln_w,
                                                  const float* __restrict__ ln_b,
                                                  const float* __restrict__ v2_w,
                                                  const float* __restrict__ v2_b) {
    __shared__ float qk[256];
    __shared__ float vv[16];
    const int b = blockIdx.x, tid = threadIdx.x;
    qk[tid] = g_qk[b * 256 + tid];
    __syncthreads();
    if (tid < 16) {
        float s = v1_b[tid];
        for (int cc = 0; cc < 256; cc++) s = fmaf(v1_w[tid * 256 + cc], qk[cc], s);
        vv[tid] = s;
    }
    __syncthreads();
    if (tid == 0) {
        float m = 0.f;
        for (int o = 0; o < 16; o++) m += vv[o];
        m *= (1.f / 16.f);
        float var = 0.f;
        for (int o = 0; o < 16; o++) { float d = vv[o] - m; var += d * d; }
        var *= (1.f / 16.f);
        float inv = rsqrtf(var + 1e-5f);
        for (int o = 0; o < 16; o++) {
            float t = (vv[o] - m) * inv * ln_w[o] + ln_b[o];
            vv[o] = fmaxf(t, 0.f);
        }
    }
    __syncthreads();
    float s = v2_b[tid];
#pragma unroll
    for (int o = 0; o < 16; o++) s = fmaf(v2_w[tid * 16 + o], vv[o], s);
    g_v[b * 256 + tid] = s;
}

// ---------------------------------------------------------------------------
// Kernel 8: out = ctx_all + v (broadcast over pixels), vectorized float4.
// ---------------------------------------------------------------------------
__global__ __launch_bounds__(256) void final_kernel(float* __restrict__ out) {
    const int idx = blockIdx.x * 256 + threadIdx.x;  // float4 index
    float4 v = ((const float4*)g_ctxall)[idx];
    float add = g_v[idx >> 10];  // 1024 float4 per (b,c) plane
    v.x += add; v.y += add; v.z += add; v.w += add;
    ((float4*)out)[idx] = v;
}

// ---------------------------------------------------------------------------
extern "C" void kernel_launch(void* const* d_in, const int* in_sizes, int n_in,
                              void* d_out, int out_size) {
    const float* x      = (const float*)d_in[0];
    const float* conv_w = (const float*)d_in[1];
    const float* conv_b = (const float*)d_in[2];
    const float* fw3    = (const float*)d_in[3];
    const float* fw5    = (const float*)d_in[4];
    const float* fw7    = (const float*)d_in[5];
    const float* key_w  = (const float*)d_in[6];
    const float* v1_w   = (const float*)d_in[8];
    const float* v1_b   = (const float*)d_in[9];
    const float* ln_w   = (const float*)d_in[10];
    const float* ln_b   = (const float*)d_in[11];
    const float* v2_w   = (const float*)d_in[12];
    const float* v2_b   = (const float*)d_in[13];
    float* out = (float*)d_out;

    gemm1_kernel<<<dim3(32, 4, 16), 128>>>(x, conv_w, conv_b);
    gates_kernel<<<dim3(16, 16, 2), 256>>>(x, conv_w, conv_b);
    gatecomb_kernel<<<256, 256>>>();
    dwchain_kernel<<<4096, 256>>>(fw3, fw5, fw7);
    key_kernel<<<dim3(16, 16, 4), 256>>>(key_w);
    softmax_kernel<<<16, 1024>>>();
    qk_kernel<<<4096, 256>>>();
    mlp_kernel<<<16, 256>>>(v1_w, v1_b, ln_w, ln_b, v2_w, v2_b);
    final_kernel<<<16384, 256>>>(out);
}

// round 11
// speedup vs baseline: 1.8859x; 1.0052x over previous
#include <cuda_runtime.h>
#include <math.h>

#define NB 16
#define NC 256
#define HW_ 4096

typedef unsigned long long u64;

// Scratch (device globals; no allocation in kernel_launch)
__device__ float g_t[NB*NC*HW_];       // ctx channels of conv1x1 output
__device__ float g_gates[NB*4*HW_];    // gate channels (fused into gemm1)
__device__ float g_ctxall[NB*NC*HW_];  // final ctx_all
__device__ float g_kp[4][NB*HW_];      // key logit partials (4-way c-split)
__device__ float g_k[NB*HW_];          // softmax result
__device__ float g_qk[NB*NC];
__device__ float g_v[NB*NC];           // broadcast add vector

__device__ __forceinline__ float gelu_f(float v) {
    return 0.5f * v * (1.0f + erff(v * 0.70710678118654752f));
}

__device__ __forceinline__ u64 pack2(float lo, float hi) {
    u64 d; asm("mov.b64 %0, {%1, %2};" : "=l"(d) : "f"(lo), "f"(hi)); return d;
}
__device__ __forceinline__ void ffma2(u64 &d, u64 a, u64 b) {
    asm("fma.rn.f32x2 %0, %1, %2, %3;" : "=l"(d) : "l"(a), "l"(b), "l"(d));
}
__device__ __forceinline__ void unpack2(float &lo, float &hi, u64 d) {
    asm("mov.b64 {%0, %1}, %2;" : "=f"(lo), "=f"(hi) : "l"(d));
}

// ---------------------------------------------------------------------------
// Kernel 1: conv1x1 main GEMM (R4/R8-measured-good core: packed f32x2 FMAs,
// scalar-LDS A broadcast + pack2, single-buffered smem) WITH the 4 gate
// output channels fused into blockIdx.y==0 blocks — gates reuse the Bs tile
// this kernel already loads, deleting the separate 256MB gates pass.
// Per batch: T(256,4096) = W(256,256) * X(256,4096); G(4,4096) on y==0.
// Tile 64(M=o) x 128(N=pixels), 128 threads, 8x8 microtile, BK=16.
// ---------------------------------------------------------------------------
__global__ __launch_bounds__(128) void gemm1_kernel(const float* __restrict__ x,
                                                    const float* __restrict__ w,
                                                    const float* __restrict__ bias) {
    __shared__ __align__(16) float As[16][64];
    __shared__ __align__(16) float Bs[16][128];
    __shared__ float wgAll[4 * 256];   // gate weights (used by y==0 blocks)
    const int b = blockIdx.z;
    const int oBase = blockIdx.y * 64;
    const int nBase = blockIdx.x * 128;
    const bool doGates = (blockIdx.y == 0);
    const float* xb = x + (size_t)b * NC * HW_;
    const int tid = threadIdx.x;
    const int tm = tid >> 4, tn = tid & 15;

    if (doGates) {
#pragma unroll
        for (int r = 0; r < 8; r++) {
            int t = tid + r * 128;                  // 0..1023
            wgAll[t] = w[(NC + (t >> 8)) * NC + (t & 255)];
        }
    }

    u64 acc2[8][4];
#pragma unroll
    for (int i = 0; i < 8; i++)
#pragma unroll
        for (int j = 0; j < 4; j++) acc2[i][j] = 0ull;
    float gacc[4];
#pragma unroll
    for (int g = 0; g < 4; g++) gacc[g] = bias[NC + g];

    for (int c0 = 0; c0 < NC; c0 += 16) {
#pragma unroll
        for (int r = 0; r < 8; r++) {
            int i = tid + r * 128;           // 0..1023
            int mm = i >> 4, kk = i & 15;
            As[kk][mm] = w[(oBase + mm) * NC + c0 + kk];
        }
#pragma unroll
        for (int kk = 0; kk < 16; kk++)
            Bs[kk][tid] = xb[(size_t)(c0 + kk) * HW_ + nBase + tid];
        __syncthreads();

#pragma unroll
        for (int kk = 0; kk < 16; kk++) {
            float4 a0 = *(const float4*)&As[kk][tm * 8];
            float4 a1 = *(const float4*)&As[kk][tm * 8 + 4];
            ulonglong2 bq0 = *(const ulonglong2*)&Bs[kk][tn * 8];
            ulonglong2 bq1 = *(const ulonglong2*)&Bs[kk][tn * 8 + 4];
            u64 bv[4] = {bq0.x, bq0.y, bq1.x, bq1.y};
            u64 a2[8];
            a2[0] = pack2(a0.x, a0.x); a2[1] = pack2(a0.y, a0.y);
            a2[2] = pack2(a0.z, a0.z); a2[3] = pack2(a0.w, a0.w);
            a2[4] = pack2(a1.x, a1.x); a2[5] = pack2(a1.y, a1.y);
            a2[6] = pack2(a1.z, a1.z); a2[7] = pack2(a1.w, a1.w);
#pragma unroll
            for (int i = 0; i < 8; i++)
#pragma unroll
                for (int j = 0; j < 4; j++)
                    ffma2(acc2[i][j], a2[i], bv[j]);
        }

        if (doGates) {
            // gate rows reuse the Bs tile: thread owns pixel nBase+tid
#pragma unroll
            for (int kk = 0; kk < 16; kk++) {
                float xv = Bs[kk][tid];
#pragma unroll
                for (int g = 0; g < 4; g++)
                    gacc[g] = fmaf(wgAll[g * 256 + c0 + kk], xv, gacc[g]);
            }
        }
        __syncthreads();
    }

#pragma unroll
    for (int i = 0; i < 8; i++) {
        int o = oBase + tm * 8 + i;
        float bvv = bias[o];
        float* dst = g_t + ((size_t)b * NC + o) * HW_ + nBase + tn * 8;
        float l0, h0, l1, h1, l2, h2, l3, h3;
        unpack2(l0, h0, acc2[i][0]); unpack2(l1, h1, acc2[i][1]);
        unpack2(l2, h2, acc2[i][2]); unpack2(l3, h3, acc2[i][3]);
        float4 v0 = make_float4(l0 + bvv, h0 + bvv, l1 + bvv, h1 + bvv);
        float4 v1 = make_float4(l2 + bvv, h2 + bvv, l3 + bvv, h3 + bvv);
        *(float4*)dst = v0;
        *(float4*)(dst + 4) = v1;
    }
    if (doGates) {
        float* gd = g_gates + (size_t)b * 4 * HW_ + nBase + tid;
#pragma unroll
        for (int g = 0; g < 4; g++) gd[g * HW_] = gacc[g];
    }
}

// ---------------------------------------------------------------------------
// Kernel 3: fused depthwise chain, scalar FMA + column-register reuse,
// 256 threads x 16 rows, capped at 64 regs (minctasm=4) for occupancy.
// (R8-measured-good: 130us, occ 46.8%)
// ---------------------------------------------------------------------------
#define PW 70  // 64 + 2*3 halo

template<int K>
__device__ __forceinline__ void conv_stage(const float* __restrict__ buf,
                                           const float* __restrict__ filt,
                                           int x0, int y0, float s[16]) {
    constexpr int YE = 16 + K - 1;
#pragma unroll
    for (int i = 0; i < 16; i++) s[i] = 0.f;
#pragma unroll
    for (int dx = 0; dx < K; dx++) {
        float col[YE];
#pragma unroll
        for (int i = 0; i < YE; i++) col[i] = buf[(y0 + i) * PW + x0 + dx];
#pragma unroll
        for (int dy = 0; dy < K; dy++) {
            const float f = filt[dy * K + dx];
#pragma unroll
            for (int i = 0; i < 16; i++) s[i] = fmaf(f, col[i + dy], s[i]);
        }
    }
}

__global__ __launch_bounds__(256, 4) void dwchain_kernel(const float* __restrict__ fw3,
                                                         const float* __restrict__ fw5,
                                                         const float* __restrict__ fw7) {
    __shared__ float buf0[PW * PW];
    __shared__ float buf1[PW * PW];
    __shared__ float filt[49];
    __shared__ float red[256];
    const int bc = blockIdx.x;              // = b*256 + c
    const int b = bc >> 8, c = bc & 255;
    const int tid = threadIdx.x;
    const int x = tid & 63, yg = tid >> 6;  // thread owns column x, rows yg*16..+15

    for (int i = tid; i < PW * PW; i += 256) { buf0[i] = 0.f; buf1[i] = 0.f; }
    if (tid < 9) filt[tid] = fw3[c * 9 + tid];
    __syncthreads();

    const float* src = g_t + (size_t)bc * HW_;
#pragma unroll
    for (int i = 0; i < 16; i++) {
        int y = yg * 16 + i;
        buf0[(y + 3) * PW + x + 3] = src[y * 64 + x];
    }
    __syncthreads();

    const float* gts = g_gates + (size_t)b * 4 * HW_;
    float acc[16];
#pragma unroll
    for (int i = 0; i < 16; i++) acc[i] = 0.f;
    float s[16];

    // --- stage 1: 3x3, buf0 -> buf1 ---
    conv_stage<3>(buf0, filt, x + 2, yg * 16 + 2, s);
#pragma unroll
    for (int i = 0; i < 16; i++) {
        int y = yg * 16 + i;
        int p = y * 64 + x;
        float g = gelu_f(s[i]);
        buf1[(y + 3) * PW + x + 3] = g;
        acc[i] = fmaf(g, gts[p], acc[i]);
    }
    __syncthreads();
    if (tid < 25) filt[tid] = fw5[c * 25 + tid];
    __syncthreads();

    // --- stage 2: 5x5, buf1 -> buf0 ---
    conv_stage<5>(buf1, filt, x + 1, yg * 16 + 1, s);
#pragma unroll
    for (int i = 0; i < 16; i++) {
        int y = yg * 16 + i;
        int p = y * 64 + x;
        float g = gelu_f(s[i]);
        buf0[(y + 3) * PW + x + 3] = g;
        acc[i] = fmaf(g, gts[HW_ + p], acc[i]);
    }
    __syncthreads();
    if (tid < 49) filt[tid] = fw7[c * 49 + tid];
    __syncthreads();

    // --- stage 3: 7x7, buf0 -> registers only, plus plane sum for global ctx ---
    conv_stage<7>(buf0, filt, x, yg * 16, s);
    float sum7 = 0.f;
#pragma unroll
    for (int i = 0; i < 16; i++) {
        int y = yg * 16 + i;
        int p = y * 64 + x;
        float g = gelu_f(s[i]);
        acc[i] = fmaf(g, gts[2 * HW_ + p], acc[i]);
        sum7 += g;
    }
    red[tid] = sum7;
    __syncthreads();
    for (int st = 128; st > 0; st >>= 1) {
        if (tid < st) red[tid] += red[tid + st];
        __syncthreads();
    }
    float mean = red[0] * (1.0f / 4096.0f);

    float* dst = g_ctxall + (size_t)bc * HW_;
#pragma unroll
    for (int i = 0; i < 16; i++) {
        int y = yg * 16 + i;
        int p = y * 64 + x;
        dst[p] = fmaf(mean, gts[3 * HW_ + p], acc[i]);
    }
}

// ---------------------------------------------------------------------------
// Kernel 4: key logit partials. 4-way channel split, bias dropped (cancels
// exactly under softmax max-subtraction).
// ---------------------------------------------------------------------------
__global__ __launch_bounds__(256) void key_kernel(const float* __restrict__ key_w) {
    __shared__ float kw[64];
    const int tid = threadIdx.x;
    const int b = blockIdx.y;
    const int part = blockIdx.z;
    const int n = blockIdx.x * 256 + tid;
    if (tid < 64) kw[tid] = key_w[part * 64 + tid];
    __syncthreads();
    const float* ca = g_ctxall + ((size_t)b * NC + part * 64) * HW_ + n;
    float a0 = 0.f, a1 = 0.f;
#pragma unroll 4
    for (int cc = 0; cc < 64; cc += 2) {
        a0 = fmaf(kw[cc], ca[(size_t)cc * HW_], a0);
        a1 = fmaf(kw[cc + 1], ca[(size_t)(cc + 1) * HW_], a1);
    }
    g_kp[part][b * HW_ + n] = a0 + a1;
}

// ---------------------------------------------------------------------------
// Kernel 5: sum partials + softmax over 4096 per batch.
// ---------------------------------------------------------------------------
__global__ __launch_bounds__(1024) void softmax_kernel() {
    __shared__ float red[1024];
    const int b = blockIdx.x, tid = threadIdx.x;
    float v[4];
    float mx = -1e30f;
#pragma unroll
    for (int i = 0; i < 4; i++) {
        int n = b * HW_ + tid + i * 1024;
        v[i] = g_kp[0][n] + g_kp[1][n] + g_kp[2][n] + g_kp[3][n];
        mx = fmaxf(mx, v[i]);
    }
    red[tid] = mx;
    __syncthreads();
    for (int st = 512; st > 0; st >>= 1) {
        if (tid < st) red[tid] = fmaxf(red[tid], red[tid + st]);
        __syncthreads();
    }
    mx = red[0];
    __syncthreads();
    float s = 0.f;
#pragma unroll
    for (int i = 0; i < 4; i++) { v[i] = expf(v[i] - mx); s += v[i]; }
    red[tid] = s;
    __syncthreads();
    for (int st = 512; st > 0; st >>= 1) {
        if (tid < st) red[tid] += red[tid + st];
        __syncthreads();
    }
    float inv = 1.0f / red[0];
#pragma unroll
    for (int i = 0; i < 4; i++) g_k[b * HW_ + tid + i * 1024] = v[i] * inv;
}

// ---------------------------------------------------------------------------
// Kernel 6: qk[b,c] = sum_n ctx_all[b,c,n] * k[b,n]  (one block per (b,c))
// ---------------------------------------------------------------------------
__global__ __launch_bounds__(256) void qk_kernel() {
    __shared__ float red[256];
    const int bc = blockIdx.x;
    const int b = bc >> 8;
    const float4* ca = (const float4*)(g_ctxall + (size_t)bc * HW_);
    const float4* kk = (const float4*)(g_k + b * HW_);
    float s = 0.f;
    for (int i = threadIdx.x; i < 1024; i += 256) {
        float4 a = ca[i], kv = kk[i];
        s += a.x * kv.x + a.y * kv.y + a.z * kv.z + a.w * kv.w;
    }
    red[threadIdx.x] = s;
    __syncthreads();
    for (int st = 128; st > 0; st >>= 1) {
        if (threadIdx.x < st) red[threadIdx.x] += red[threadIdx.x + st];
        __syncthreads();
    }
    if (threadIdx.x == 0) g_qk[bc] = red[0];
}

// ---------------------------------------------------------------------------
// Kernel 7: per-batch tiny MLP: v1 (16) -> layernorm -> relu -> v2 (256)
// ---------------------------------------------------------------------------
__global__ __launch_bounds__(256) void mlp_kernel(const float* __restrict__ v1_w,
                                                  const float* __restrict__ v1_b,
                                                  const float* __restrict__ ln_w,
                                                  const float* __restrict__ ln_b,
                                                  const float* __restrict__ v2_w,
                                                  const float* __restrict__ v2_b) {
    __shared__ float qk[256];
    __shared__ float vv[16];
    const int b = blockIdx.x, tid = threadIdx.x;
    qk[tid] = g_qk[b * 256 + tid];
    __syncthreads();
    if (tid < 16) {
        float s = v1_b[tid];
        for (int cc = 0; cc < 256; cc++) s = fmaf(v1_w[tid * 256 + cc], qk[cc], s);
        vv[tid] = s;
    }
    __syncthreads();
    if (tid == 0) {
        float m = 0.f;
        for (int o = 0; o < 16; o++) m += vv[o];
        m *= (1.f / 16.f);
        float var = 0.f;
        for (int o = 0; o < 16; o++) { float d = vv[o] - m; var += d * d; }
        var *= (1.f / 16.f);
        float inv = rsqrtf(var + 1e-5f);
        for (int o = 0; o < 16; o++) {
            float t = (vv[o] - m) * inv * ln_w[o] + ln_b[o];
            vv[o] = fmaxf(t, 0.f);
        }
    }
    __syncthreads();
    float s = v2_b[tid];
#pragma unroll
    for (int o = 0; o < 16; o++) s = fmaf(v2_w[tid * 16 + o], vv[o], s);
    g_v[b * 256 + tid] = s;
}

// ---------------------------------------------------------------------------
// Kernel 8: out = ctx_all + v (broadcast over pixels), vectorized float4.
// ---------------------------------------------------------------------------
__global__ __launch_bounds__(256) void final_kernel(float* __restrict__ out) {
    const int idx = blockIdx.x * 256 + threadIdx.x;  // float4 index
    float4 v = ((const float4*)g_ctxall)[idx];
    float add = g_v[idx >> 10];  // 1024 float4 per (b,c) plane
    v.x += add; v.y += add; v.z += add; v.w += add;
    ((float4*)out)[idx] = v;
}

// ---------------------------------------------------------------------------
extern "C" void kernel_launch(void* const* d_in, const int* in_sizes, int n_in,
                              void* d_out, int out_size) {
    const float* x      = (const float*)d_in[0];
    const float* conv_w = (const float*)d_in[1];
    const float* conv_b = (const float*)d_in[2];
    const float* fw3    = (const float*)d_in[3];
    const float* fw5    = (const float*)d_in[4];
    const float* fw7    = (const float*)d_in[5];
    const float* key_w  = (const float*)d_in[6];
    const float* v1_w   = (const float*)d_in[8];
    const float* v1_b   = (const float*)d_in[9];
    const float* ln_w   = (const float*)d_in[10];
    const float* ln_b   = (const float*)d_in[11];
    const float* v2_w   = (const float*)d_in[12];
    const float* v2_b   = (const float*)d_in[13];
    float* out = (float*)d_out;

    gemm1_kernel<<<dim3(32, 4, 16), 128>>>(x, conv_w, conv_b);
    dwchain_kernel<<<4096, 256>>>(fw3, fw5, fw7);
    key_kernel<<<dim3(16, 16, 4), 256>>>(key_w);
    softmax_kernel<<<16, 1024>>>();
    qk_kernel<<<4096, 256>>>();
    mlp_kernel<<<16, 256>>>(v1_w, v1_b, ln_w, ln_b, v2_w, v2_b);
    final_kernel<<<16384, 256>>>(out);
}